// round 15
// baseline (speedup 1.0000x reference)
#include <cuda_runtime.h>
#include <cuda_bf16.h>
#include <cstdint>

#define BB 4
#define LL 4096
#define HH 16
#define DD 128
#define BH (BB*HH)
#define QSPLITS 32
#define KSPLITS 8
#define LSPLIT (LL/KSPLITS)    // 512
#define NCH (LSPLIT/32)        // 16 chunks of 32 rows
#define STRIDE_L (HH*DD)
#define EPS 1e-6f

// ---------------- scratch ----------------
__device__ float g_qpart[BH*QSPLITS*DD];
__device__ float g_alpha[BH*LL];
__device__ float g_kvpart[(size_t)BH*KSPLITS*DD*DD];
__device__ float g_ksumpart[BH*KSPLITS*DD];
__device__ float g_ksum[BH*DD];
__device__ unsigned g_kvT_hi[BH*DD*(DD/2)];
__device__ unsigned g_kvT_lo[BH*DD*(DD/2)];

__device__ __forceinline__ size_t head_base(int bh) {
    return (size_t)(bh >> 4) * LL * STRIDE_L + (size_t)(bh & 15) * DD;
}
__device__ __forceinline__ unsigned smem_u32(const void* p) {
    unsigned a;
    asm("{ .reg .u64 t; cvta.to.shared.u64 t, %1; cvt.u32.u64 %0, t; }" : "=r"(a) : "l"(p));
    return a;
}
__device__ __forceinline__ unsigned swz256(unsigned off){ return off ^ (((off >> 8) & 7) << 4); }
// 64B-row swizzle, conflict-free: bits[6:4] ^= bits[8:6]
__device__ __forceinline__ unsigned sw64b(unsigned off) { return off ^ ((off >> 2) & 0x70); }

__device__ __forceinline__ void cvt2_hilo(float x0, float x1, unsigned& hi, unsigned& lo) {
    asm("cvt.rn.bf16x2.f32 %0, %1, %2;" : "=r"(hi) : "f"(x1), "f"(x0));
    float h0 = __uint_as_float(hi << 16);
    float h1 = __uint_as_float(hi & 0xffff0000u);
    asm("cvt.rn.bf16x2.f32 %0, %1, %2;" : "=r"(lo) : "f"(x1 - h1), "f"(x0 - h0));
}
__device__ __forceinline__ void cpa16(unsigned dst, const void* src) {
    asm volatile("cp.async.cg.shared.global [%0], [%1], 16;" :: "r"(dst), "l"(src));
}
__device__ __forceinline__ void cpa_commit() { asm volatile("cp.async.commit_group;" ::: "memory"); }
__device__ __forceinline__ void cpa_wait0()  { asm volatile("cp.async.wait_group 0;" ::: "memory"); }
__device__ __forceinline__ void ldsm4(unsigned r[4], unsigned addr) {
    asm volatile("ldmatrix.sync.aligned.m8n8.x4.shared.b16 {%0,%1,%2,%3}, [%4];"
        : "=r"(r[0]), "=r"(r[1]), "=r"(r[2]), "=r"(r[3]) : "r"(addr));
}
__device__ __forceinline__ void ldsm4t(unsigned r[4], unsigned addr) {
    asm volatile("ldmatrix.sync.aligned.m8n8.x4.trans.shared.b16 {%0,%1,%2,%3}, [%4];"
        : "=r"(r[0]), "=r"(r[1]), "=r"(r[2]), "=r"(r[3]) : "r"(addr));
}
__device__ __forceinline__ void mma16816(float c[4], const unsigned a[4], unsigned b0, unsigned b1) {
    asm volatile("mma.sync.aligned.m16n8k16.row.col.f32.bf16.bf16.f32 "
        "{%0,%1,%2,%3}, {%4,%5,%6,%7}, {%8,%9}, {%0,%1,%2,%3};"
        : "+f"(c[0]), "+f"(c[1]), "+f"(c[2]), "+f"(c[3])
        : "r"(a[0]), "r"(a[1]), "r"(a[2]), "r"(a[3]), "r"(b0), "r"(b1));
}

// ---------------- K1: partial sums of Q ----------------
__global__ void k_qsum(const float* __restrict__ Q) {
    int split = blockIdx.x, bh = blockIdx.y, d = threadIdx.x;
    const float* p = Q + head_base(bh) + (size_t)split * (LL/QSPLITS) * STRIDE_L + d;
    float acc = 0.f;
#pragma unroll 8
    for (int l = 0; l < LL/QSPLITS; l++) acc += p[(size_t)l * STRIDE_L];
    g_qpart[(bh * QSPLITS + split) * DD + d] = acc;
}

// ---------------- K3: scores (q_global reduction fused) ----------------
__global__ void k_scores(const float* __restrict__ K) {
    __shared__ float4 qg[32];
    int bh = blockIdx.x, tid = threadIdx.x;
    if (tid < 32) {
        float4 s = make_float4(0.f, 0.f, 0.f, 0.f);
#pragma unroll
        for (int sp = 0; sp < QSPLITS; sp++) {
            float4 v = ((const float4*)(g_qpart + (bh * QSPLITS + sp) * DD))[tid];
            s.x += v.x; s.y += v.y; s.z += v.z; s.w += v.w;
        }
        float sc = (1.0f / (float)LL) * rsqrtf(2048.0f);
        s.x *= sc; s.y *= sc; s.z *= sc; s.w *= sc;
        qg[tid] = s;
    }
    __syncthreads();
    int w = tid >> 5, lane = tid & 31;
    int l = blockIdx.y * 8 + w;
    const float4* kp = (const float4*)(K + head_base(bh) + (size_t)l * STRIDE_L);
    float4 kv = kp[lane];
    float4 q = qg[lane];
    float s = kv.x * q.x + kv.y * q.y + kv.z * q.z + kv.w * q.w;
#pragma unroll
    for (int o = 16; o; o >>= 1) s += __shfl_xor_sync(0xffffffffu, s, o);
    if (lane == 0) g_alpha[bh * LL + l] = s;
}

// ---------------- K4: softmax, register-resident ----------------
__global__ void __launch_bounds__(1024) k_softmax() {
    __shared__ float red[32];
    int bh = blockIdx.x, tid = threadIdx.x;
    int w = tid >> 5, lane = tid & 31;
    float4* s4 = (float4*)(g_alpha + bh * LL);
    float4 v = s4[tid];
    float m = fmaxf(fmaxf(v.x, v.y), fmaxf(v.z, v.w));
#pragma unroll
    for (int o = 16; o; o >>= 1) m = fmaxf(m, __shfl_xor_sync(0xffffffffu, m, o));
    if (lane == 0) red[w] = m;
    __syncthreads();
    m = red[lane & 31];
#pragma unroll
    for (int o = 16; o; o >>= 1) m = fmaxf(m, __shfl_xor_sync(0xffffffffu, m, o));
    float e0 = __expf(v.x - m), e1 = __expf(v.y - m);
    float e2 = __expf(v.z - m), e3 = __expf(v.w - m);
    float sum = e0 + e1 + e2 + e3;
#pragma unroll
    for (int o = 16; o; o >>= 1) sum += __shfl_xor_sync(0xffffffffu, sum, o);
    __syncthreads();
    if (lane == 0) red[w] = sum;
    __syncthreads();
    sum = red[lane & 31];
#pragma unroll
    for (int o = 16; o; o >>= 1) sum += __shfl_xor_sync(0xffffffffu, sum, o);
    float scale = (float)LL / sum;
    s4[tid] = make_float4(e0 * scale, e1 * scale, e2 * scale, e3 * scale);
}

// ---------------- K5: cp.async-staged HMMA split-K GEMM ----------------
// grid (KSPLITS, BH), block 256, dyn smem 100352
__global__ void __launch_bounds__(256, 2) k5_gemm(const float* __restrict__ phiK,
                                                  const float* __restrict__ V) {
    extern __shared__ __align__(16) unsigned char smb[];
    unsigned sbase = smem_u32(smb);
    const unsigned STGPK = 65536u, STGV = 81920u, ALF = 98304u;

    int split = blockIdx.x, bh = blockIdx.y, tid = threadIdx.x;
    int wid = tid >> 5, lane = tid & 31;
    int warpM = (wid >> 1) * 32, warpN = (wid & 1) * 64;
    size_t base = head_base(bh);
    int c16 = tid & 31, rgrp = tid >> 5;

    for (int i = tid; i < LSPLIT; i += 256)
        ((float*)(smb + ALF))[i] = g_alpha[bh * LL + split * LSPLIT + i];

    float acc[2][8][4];
#pragma unroll
    for (int mt = 0; mt < 2; mt++)
#pragma unroll
        for (int nt = 0; nt < 8; nt++)
#pragma unroll
            for (int c = 0; c < 4; c++) acc[mt][nt][c] = 0.f;
    float ksa[4] = {0.f, 0.f, 0.f, 0.f};

#define K5_CPA(CH) do {                                                          \
    int lb_ = split * LSPLIT + (CH) * 32;                                        \
    _Pragma("unroll")                                                            \
    for (int it = 0; it < 4; it++) {                                             \
        int row = rgrp + it * 8;                                                 \
        unsigned so = (unsigned)(row * 512 + c16 * 16);                          \
        cpa16(sbase + STGPK + so, phiK + base + (size_t)(lb_ + row) * STRIDE_L + c16 * 4); \
        cpa16(sbase + STGV  + so, V    + base + (size_t)(lb_ + row) * STRIDE_L + c16 * 4); \
    }                                                                            \
    cpa_commit();                                                                \
} while (0)

#define K5_CVT(CH, B) do {                                                       \
    unsigned bo_ = (unsigned)(B) * 32768u;                                       \
    _Pragma("unroll")                                                            \
    for (int it = 0; it < 4; it++) {                                             \
        int row = rgrp + it * 8;                                                 \
        unsigned so = (unsigned)(row * 512 + c16 * 16);                          \
        float a = ((float*)(smb + ALF))[(CH) * 32 + row];                        \
        float4 pk = *(float4*)(smb + STGPK + so);                                \
        float4 vv = *(float4*)(smb + STGV + so);                                 \
        pk.x *= a; pk.y *= a; pk.z *= a; pk.w *= a;                              \
        ksa[0] += pk.x; ksa[1] += pk.y; ksa[2] += pk.z; ksa[3] += pk.w;          \
        unsigned h01, l01, h23, l23;                                             \
        unsigned off = bo_ + swz256((unsigned)(row * 256 + c16 * 8));            \
        cvt2_hilo(pk.x, pk.y, h01, l01); cvt2_hilo(pk.z, pk.w, h23, l23);        \
        *(uint2*)(smb + off)          = make_uint2(h01, h23);                    \
        *(uint2*)(smb + off + 8192)   = make_uint2(l01, l23);                    \
        cvt2_hilo(vv.x, vv.y, h01, l01); cvt2_hilo(vv.z, vv.w, h23, l23);        \
        *(uint2*)(smb + off + 16384)  = make_uint2(h01, h23);                    \
        *(uint2*)(smb + off + 24576)  = make_uint2(l01, l23);                    \
    }                                                                            \
} while (0)

    K5_CPA(0);
    cpa_wait0();
    K5_CVT(0, 0);
    __syncthreads();

    for (int ch = 0; ch < NCH; ch++) {
        if (ch + 1 < NCH) K5_CPA(ch + 1);
        unsigned bo = (unsigned)(ch & 1) * 32768u;
#pragma unroll
        for (int kk = 0; kk < 2; kk++) {
            unsigned ah[2][4], al[2][4];
#pragma unroll
            for (int mt = 0; mt < 2; mt++) {
                unsigned row = kk * 16 + ((lane >> 4) & 1) * 8 + (lane & 7);
                unsigned col = (warpM + mt * 16) * 2 + ((lane >> 3) & 1) * 16;
                unsigned aoff = bo + swz256(row * 256 + col);
                ldsm4t(ah[mt], sbase + aoff);
                ldsm4t(al[mt], sbase + aoff + 8192);
            }
#pragma unroll
            for (int np = 0; np < 4; np++) {
                unsigned bhr[4], blr[4];
                unsigned brow = kk * 16 + ((lane >> 3) & 1) * 8 + (lane & 7);
                unsigned bcol = (warpN + np * 16) * 2 + ((lane >> 4) & 1) * 16;
                unsigned boff = bo + swz256(brow * 256 + bcol);
                ldsm4t(bhr, sbase + boff + 16384);
                ldsm4t(blr, sbase + boff + 24576);
#pragma unroll
                for (int mt = 0; mt < 2; mt++) {
                    mma16816(acc[mt][np*2],   ah[mt], bhr[0], bhr[1]);
                    mma16816(acc[mt][np*2+1], ah[mt], bhr[2], bhr[3]);
                }
#pragma unroll
                for (int mt = 0; mt < 2; mt++) {
                    mma16816(acc[mt][np*2],   al[mt], bhr[0], bhr[1]);
                    mma16816(acc[mt][np*2+1], al[mt], bhr[2], bhr[3]);
                }
#pragma unroll
                for (int mt = 0; mt < 2; mt++) {
                    mma16816(acc[mt][np*2],   ah[mt], blr[0], blr[1]);
                    mma16816(acc[mt][np*2+1], ah[mt], blr[2], blr[3]);
                }
            }
        }
        if (ch + 1 < NCH) {
            cpa_wait0();
            K5_CVT(ch + 1, (ch + 1) & 1);
        }
        __syncthreads();
    }

    float* dstb = g_kvpart + (size_t)(bh * KSPLITS + split) * DD * DD;
    int g = lane >> 2, qc = (lane & 3) * 2;
#pragma unroll
    for (int mt = 0; mt < 2; mt++)
#pragma unroll
        for (int nt = 0; nt < 8; nt++) {
            int row = warpM + mt * 16 + g;
            int col = warpN + nt * 8 + qc;
            *(float2*)&dstb[(size_t)row * DD + col]       = make_float2(acc[mt][nt][0], acc[mt][nt][1]);
            *(float2*)&dstb[(size_t)(row + 8) * DD + col] = make_float2(acc[mt][nt][2], acc[mt][nt][3]);
        }

    *(float4*)(smb + STGPK + (rgrp * DD + c16 * 4) * 4) = make_float4(ksa[0], ksa[1], ksa[2], ksa[3]);
    __syncthreads();
    if (tid < 32) {
        float4 s = make_float4(0.f, 0.f, 0.f, 0.f);
#pragma unroll
        for (int r = 0; r < 8; r++) {
            float4 v = *(float4*)(smb + STGPK + (r * DD + tid * 4) * 4);
            s.x += v.x; s.y += v.y; s.z += v.z; s.w += v.w;
        }
        *(float4*)(g_ksumpart + (bh * KSPLITS + split) * DD + tid * 4) = s;
    }
}

// ---------------- K6: parallel reduce -> ksum + KVT bf16 hi/lo ----------------
__global__ void __launch_bounds__(256) k6_reduce() {
    __shared__ float accT[32][129];
    __shared__ unsigned oh[32][64];
    __shared__ unsigned ol[32][64];

    int ex = blockIdx.x, bh = blockIdx.y, tid = threadIdx.x;
    int e0 = ex * 32;

    for (int idx = tid; idx < 128 * 32; idx += 256) {
        int d = idx >> 5, el = idx & 31;
        float s = 0.f;
#pragma unroll
        for (int sp = 0; sp < KSPLITS; sp++)
            s += g_kvpart[(size_t)(bh * KSPLITS + sp) * DD * DD + d * DD + e0 + el];
        accT[el][d] = s;
    }
    if (ex == 0 && tid < DD) {
        float s = 0.f;
#pragma unroll
        for (int sp = 0; sp < KSPLITS; sp++) s += g_ksumpart[(bh * KSPLITS + sp) * DD + tid];
        g_ksum[bh * DD + tid] = s;
    }
    __syncthreads();
    for (int idx = tid; idx < 32 * 64; idx += 256) {
        int el = idx >> 6, i = idx & 63;
        unsigned hi, lo;
        cvt2_hilo(accT[el][2 * i], accT[el][2 * i + 1], hi, lo);
        oh[el][i] = hi;
        ol[el][i] = lo;
    }
    __syncthreads();
    for (int idx = tid; idx < 32 * 64; idx += 256) {
        int el = idx >> 6, c = idx & 63;
        size_t di = (size_t)(bh * DD + e0 + el) * (DD/2) + c;
        g_kvT_hi[di] = oh[el][c];
        g_kvT_lo[di] = ol[el][c];
    }
}

// ---------------- K7: resident-B, double-buffered-A, cp.async HMMA GEMM ----------------
// grid (LL/128, BH), block 256, dyn smem 114688
__global__ void __launch_bounds__(256, 2) k7_gemm(const float* __restrict__ phiQ,
                                                  float* __restrict__ out) {
    extern __shared__ __align__(16) unsigned char smb[];
    unsigned sbase = smem_u32(smb);
    __shared__ float sden[DD];
    __shared__ float ksp[DD];
    const unsigned BLOQ = 32768u, AB = 65536u, STGQ = 98304u;

    int chunk = blockIdx.x, bh = blockIdx.y, tid = threadIdx.x;
    int wid = tid >> 5, lane = tid & 31;
    int warpM = (wid >> 1) * 32, warpN = (wid & 1) * 64;
    size_t base = head_base(bh);
    int l0 = chunk * 128;

    if (tid < DD) ksp[tid] = g_ksum[bh * DD + tid];
    for (int idx = tid; idx < 2048; idx += 256) {
        int r = idx >> 4, c16 = idx & 15;
        size_t src = (size_t)(bh * DD + r) * (DD/2) + c16 * 4;
        unsigned off = swz256((unsigned)(r * 256 + c16 * 16));
        *(uint4*)(smb + off)        = *(const uint4*)(g_kvT_hi + src);
        *(uint4*)(smb + BLOQ + off) = *(const uint4*)(g_kvT_lo + src);
    }

    float acc[2][8][4];
#pragma unroll
    for (int mt = 0; mt < 2; mt++)
#pragma unroll
        for (int nt = 0; nt < 8; nt++)
#pragma unroll
            for (int c = 0; c < 4; c++) acc[mt][nt][c] = 0.f;
    float denAcc[4] = {0.f, 0.f, 0.f, 0.f};

#define K7_CPA(CH) do {                                                               \
    _Pragma("unroll")                                                                 \
    for (int it = 0; it < 4; it++) {                                                  \
        int idx = tid + it * 256;                                                     \
        int row = idx >> 3, c4 = idx & 7;                                             \
        cpa16(sbase + STGQ + (unsigned)(row * 128 + c4 * 16),                         \
              phiQ + base + (size_t)(l0 + row) * STRIDE_L + (CH) * 32 + c4 * 4);      \
    }                                                                                 \
    cpa_commit();                                                                     \
} while (0)

#define K7_CVT(CH, B_) do {                                                           \
    unsigned ab_ = AB + (unsigned)(B_) * 16384u;                                      \
    _Pragma("unroll")                                                                 \
    for (int it = 0; it < 4; it++) {                                                  \
        int idx = tid + it * 256;                                                     \
        int row = idx >> 3, c4 = idx & 7;                                             \
        int dg = (CH) * 32 + c4 * 4;                                                  \
        float4 v = *(float4*)(smb + STGQ + (unsigned)(row * 128 + c4 * 16));          \
        float p = v.x * ksp[dg] + v.y * ksp[dg+1] + v.z * ksp[dg+2] + v.w * ksp[dg+3];\
        p += __shfl_xor_sync(0xffffffffu, p, 4);                                      \
        p += __shfl_xor_sync(0xffffffffu, p, 2);                                      \
        p += __shfl_xor_sync(0xffffffffu, p, 1);                                      \
        denAcc[it] += p;                                                              \
        unsigned h01, l01, h23, l23;                                                  \
        cvt2_hilo(v.x, v.y, h01, l01);                                                \
        cvt2_hilo(v.z, v.w, h23, l23);                                                \
        unsigned off = ab_ + sw64b((unsigned)(row * 64 + c4 * 8));                    \
        *(uint2*)(smb + off)        = make_uint2(h01, h23);                           \
        *(uint2*)(smb + off + 8192) = make_uint2(l01, l23);                           \
    }                                                                                 \
} while (0)

    K7_CPA(0);

    for (int ch = 0; ch < 4; ch++) {
        cpa_wait0();
        K7_CVT(ch, ch & 1);
        __syncthreads();
        if (ch + 1 < 4) K7_CPA(ch + 1);
        unsigned ab = AB + (unsigned)(ch & 1) * 16384u;
#pragma unroll
        for (int kk = 0; kk < 2; kk++) {
            unsigned ah[2][4], al[2][4];
#pragma unroll
            for (int mt = 0; mt < 2; mt++) {
                unsigned aoff = ab + sw64b((warpM + mt * 16 + (lane & 15)) * 64
                                           + kk * 32 + (lane >> 4) * 16);
                ldsm4(ah[mt], sbase + aoff);
                ldsm4(al[mt], sbase + aoff + 8192);
            }
#pragma unroll
            for (int np = 0; np < 4; np++) {
                unsigned bhr[4], blr[4];
                unsigned boff = swz256((warpN + (np * 2 + (lane >> 4)) * 8 + (lane & 7)) * 256
                                       + ch * 64 + kk * 32 + ((lane >> 3) & 1) * 16);
                ldsm4(bhr, sbase + boff);
                ldsm4(blr, sbase + boff + BLOQ);
#pragma unroll
                for (int mt = 0; mt < 2; mt++) {
                    mma16816(acc[mt][np*2],   ah[mt], bhr[0], bhr[1]);
                    mma16816(acc[mt][np*2+1], ah[mt], bhr[2], bhr[3]);
                }
#pragma unroll
                for (int mt = 0; mt < 2; mt++) {
                    mma16816(acc[mt][np*2],   al[mt], bhr[0], bhr[1]);
                    mma16816(acc[mt][np*2+1], al[mt], bhr[2], bhr[3]);
                }
#pragma unroll
                for (int mt = 0; mt < 2; mt++) {
                    mma16816(acc[mt][np*2],   ah[mt], blr[0], blr[1]);
                    mma16816(acc[mt][np*2+1], ah[mt], blr[2], blr[3]);
                }
            }
        }
    }

    __syncthreads();
    if ((tid & 7) == 0) {
#pragma unroll
        for (int it = 0; it < 4; it++) sden[(tid >> 3) + it * 32] = denAcc[it] + EPS;
    }
    __syncthreads();

    int g = lane >> 2, qc = (lane & 3) * 2;
#pragma unroll
    for (int mt = 0; mt < 2; mt++) {
        int row = warpM + mt * 16 + g;
        float d0 = 1.0f / sden[row], d1 = 1.0f / sden[row + 8];
#pragma unroll
        for (int nt = 0; nt < 8; nt++) {
            int col = warpN + nt * 8 + qc;
            float* p0 = out + base + (size_t)(l0 + row) * STRIDE_L + col;
            float* p1 = out + base + (size_t)(l0 + row + 8) * STRIDE_L + col;
            *(float2*)p0 = make_float2(acc[mt][nt][0] * d0, acc[mt][nt][1] * d0);
            *(float2*)p1 = make_float2(acc[mt][nt][2] * d1, acc[mt][nt][3] * d1);
        }
    }
}

// ---------------- launch ----------------
extern "C" void kernel_launch(void* const* d_in, const int* in_sizes, int n_in,
                              void* d_out, int out_size) {
    const float* Q    = (const float*)d_in[0];
    const float* K    = (const float*)d_in[1];
    const float* V    = (const float*)d_in[2];
    const float* phiQ = (const float*)d_in[3];
    const float* phiK = (const float*)d_in[4];
    float* out = (float*)d_out;

    static bool attr_set = false;
    if (!attr_set) {
        cudaFuncSetAttribute(k5_gemm, cudaFuncAttributeMaxDynamicSharedMemorySize, 100352);
        cudaFuncSetAttribute(k7_gemm, cudaFuncAttributeMaxDynamicSharedMemorySize, 114688);
        attr_set = true;
    }

    k_qsum<<<dim3(QSPLITS, BH), 128>>>(Q);
    k_scores<<<dim3(BH, LL / 8), 256>>>(K);
    k_softmax<<<BH, 1024>>>();
    k5_gemm<<<dim3(KSPLITS, BH), 256, 100352>>>(phiK, V);
    k6_reduce<<<dim3(4, BH), 256>>>();
    k7_gemm<<<dim3(LL/128, BH), 256, 114688>>>(phiQ, out);
}

// round 16
// speedup vs baseline: 1.0727x; 1.0727x over previous
#include <cuda_runtime.h>
#include <cuda_bf16.h>
#include <cstdint>

#define BB 4
#define LL 4096
#define HH 16
#define DD 128
#define BH (BB*HH)
#define QSPLITS 8
#define KSPLITS 8
#define LSPLIT (LL/KSPLITS)    // 512
#define NCH (LSPLIT/32)        // 16 chunks of 32 rows
#define STRIDE_L (HH*DD)
#define EPS 1e-6f

// ---------------- scratch ----------------
__device__ float g_qpart[BH*QSPLITS*DD];
__device__ float g_alpha[BH*LL];        // raw scores (softmax fused into k5)
__device__ float g_kvpart[(size_t)BH*KSPLITS*DD*DD];
__device__ float g_ksumpart[BH*KSPLITS*DD];
__device__ float g_ksum[BH*DD];
__device__ unsigned g_kvT_hi[BH*DD*(DD/2)];
__device__ unsigned g_kvT_lo[BH*DD*(DD/2)];

__device__ __forceinline__ size_t head_base(int bh) {
    return (size_t)(bh >> 4) * LL * STRIDE_L + (size_t)(bh & 15) * DD;
}
__device__ __forceinline__ unsigned smem_u32(const void* p) {
    unsigned a;
    asm("{ .reg .u64 t; cvta.to.shared.u64 t, %1; cvt.u32.u64 %0, t; }" : "=r"(a) : "l"(p));
    return a;
}
__device__ __forceinline__ unsigned swz256(unsigned off){ return off ^ (((off >> 8) & 7) << 4); }
__device__ __forceinline__ unsigned sw64b(unsigned off) { return off ^ ((off >> 2) & 0x70); }

__device__ __forceinline__ void cvt2_hilo(float x0, float x1, unsigned& hi, unsigned& lo) {
    asm("cvt.rn.bf16x2.f32 %0, %1, %2;" : "=r"(hi) : "f"(x1), "f"(x0));
    float h0 = __uint_as_float(hi << 16);
    float h1 = __uint_as_float(hi & 0xffff0000u);
    asm("cvt.rn.bf16x2.f32 %0, %1, %2;" : "=r"(lo) : "f"(x1 - h1), "f"(x0 - h0));
}
__device__ __forceinline__ void cpa16(unsigned dst, const void* src) {
    asm volatile("cp.async.cg.shared.global [%0], [%1], 16;" :: "r"(dst), "l"(src));
}
__device__ __forceinline__ void cpa_commit() { asm volatile("cp.async.commit_group;" ::: "memory"); }
__device__ __forceinline__ void cpa_wait0()  { asm volatile("cp.async.wait_group 0;" ::: "memory"); }
__device__ __forceinline__ void ldsm4(unsigned r[4], unsigned addr) {
    asm volatile("ldmatrix.sync.aligned.m8n8.x4.shared.b16 {%0,%1,%2,%3}, [%4];"
        : "=r"(r[0]), "=r"(r[1]), "=r"(r[2]), "=r"(r[3]) : "r"(addr));
}
__device__ __forceinline__ void ldsm4t(unsigned r[4], unsigned addr) {
    asm volatile("ldmatrix.sync.aligned.m8n8.x4.trans.shared.b16 {%0,%1,%2,%3}, [%4];"
        : "=r"(r[0]), "=r"(r[1]), "=r"(r[2]), "=r"(r[3]) : "r"(addr));
}
__device__ __forceinline__ void mma16816(float c[4], const unsigned a[4], unsigned b0, unsigned b1) {
    asm volatile("mma.sync.aligned.m16n8k16.row.col.f32.bf16.bf16.f32 "
        "{%0,%1,%2,%3}, {%4,%5,%6,%7}, {%8,%9}, {%0,%1,%2,%3};"
        : "+f"(c[0]), "+f"(c[1]), "+f"(c[2]), "+f"(c[3])
        : "r"(a[0]), "r"(a[1]), "r"(a[2]), "r"(a[3]), "r"(b0), "r"(b1));
}

// ---------------- K1: partial sums of Q ----------------
__global__ void k_qsum(const float* __restrict__ Q) {
    int split = blockIdx.x, bh = blockIdx.y, d = threadIdx.x;
    const float* p = Q + head_base(bh) + (size_t)split * (LL/QSPLITS) * STRIDE_L + d;
    float acc = 0.f;
#pragma unroll 8
    for (int l = 0; l < LL/QSPLITS; l++) acc += p[(size_t)l * STRIDE_L];
    g_qpart[(bh * QSPLITS + split) * DD + d] = acc;
}

// ---------------- K3: scores (q_global reduction fused) ----------------
__global__ void k_scores(const float* __restrict__ K) {
    __shared__ float4 qg[32];
    int bh = blockIdx.x, tid = threadIdx.x;
    if (tid < 32) {
        float4 s = make_float4(0.f, 0.f, 0.f, 0.f);
#pragma unroll
        for (int sp = 0; sp < QSPLITS; sp++) {
            float4 v = ((const float4*)(g_qpart + (bh * QSPLITS + sp) * DD))[tid];
            s.x += v.x; s.y += v.y; s.z += v.z; s.w += v.w;
        }
        float sc = (1.0f / (float)LL) * rsqrtf(2048.0f);
        s.x *= sc; s.y *= sc; s.z *= sc; s.w *= sc;
        qg[tid] = s;
    }
    __syncthreads();
    int w = tid >> 5, lane = tid & 31;
    int l = blockIdx.y * 8 + w;
    const float4* kp = (const float4*)(K + head_base(bh) + (size_t)l * STRIDE_L);
    float4 kv = kp[lane];
    float4 q = qg[lane];
    float s = kv.x * q.x + kv.y * q.y + kv.z * q.z + kv.w * q.w;
#pragma unroll
    for (int o = 16; o; o >>= 1) s += __shfl_xor_sync(0xffffffffu, s, o);
    if (lane == 0) g_alpha[bh * LL + l] = s;
}

// ---------------- K5: fused-softmax, cp.async-staged HMMA split-K GEMM ----------------
// grid (KSPLITS, BH), block 256, dyn smem 100352
__global__ void __launch_bounds__(256, 2) k5_gemm(const float* __restrict__ phiK,
                                                  const float* __restrict__ V) {
    extern __shared__ __align__(16) unsigned char smb[];
    unsigned sbase = smem_u32(smb);
    const unsigned STGPK = 65536u, STGV = 81920u, ALF = 98304u;

    int split = blockIdx.x, bh = blockIdx.y, tid = threadIdx.x;
    int wid = tid >> 5, lane = tid & 31;
    int warpM = (wid >> 1) * 32, warpN = (wid & 1) * 64;
    size_t base = head_base(bh);
    int c16 = tid & 31, rgrp = tid >> 5;

    // ---- fused softmax prologue (deterministic, identical across splits) ----
    {
        float* red = (float*)(smb + STGPK);      // 16 floats, staging reused
        const float4* sc4 = (const float4*)(g_alpha + bh * LL);
        float4 sv[4];
#pragma unroll
        for (int it = 0; it < 4; it++) sv[it] = sc4[tid + it * 256];
        float m = -1e30f;
#pragma unroll
        for (int it = 0; it < 4; it++)
            m = fmaxf(m, fmaxf(fmaxf(sv[it].x, sv[it].y), fmaxf(sv[it].z, sv[it].w)));
#pragma unroll
        for (int o = 16; o; o >>= 1) m = fmaxf(m, __shfl_xor_sync(0xffffffffu, m, o));
        if (lane == 0) red[wid] = m;
        __syncthreads();
        m = red[0];
#pragma unroll
        for (int r = 1; r < 8; r++) m = fmaxf(m, red[r]);
        float sum = 0.f;
#pragma unroll
        for (int it = 0; it < 4; it++) {
            sum += __expf(sv[it].x - m) + __expf(sv[it].y - m)
                 + __expf(sv[it].z - m) + __expf(sv[it].w - m);
        }
#pragma unroll
        for (int o = 16; o; o >>= 1) sum += __shfl_xor_sync(0xffffffffu, sum, o);
        __syncthreads();
        if (lane == 0) red[8 + wid] = sum;
        __syncthreads();
        sum = 0.f;
#pragma unroll
        for (int r = 0; r < 8; r++) sum += red[8 + r];
        float scale = (float)LL / sum;
        const float* sc = g_alpha + bh * LL + split * LSPLIT;
        for (int i = tid; i < LSPLIT; i += 256)
            ((float*)(smb + ALF))[i] = __expf(sc[i] - m) * scale;
    }
    __syncthreads();   // ALF visible to all; staging free for cp.async

    float acc[2][8][4];
#pragma unroll
    for (int mt = 0; mt < 2; mt++)
#pragma unroll
        for (int nt = 0; nt < 8; nt++)
#pragma unroll
            for (int c = 0; c < 4; c++) acc[mt][nt][c] = 0.f;
    float ksa[4] = {0.f, 0.f, 0.f, 0.f};

#define K5_CPA(CH) do {                                                          \
    int lb_ = split * LSPLIT + (CH) * 32;                                        \
    _Pragma("unroll")                                                            \
    for (int it = 0; it < 4; it++) {                                             \
        int row = rgrp + it * 8;                                                 \
        unsigned so = (unsigned)(row * 512 + c16 * 16);                          \
        cpa16(sbase + STGPK + so, phiK + base + (size_t)(lb_ + row) * STRIDE_L + c16 * 4); \
        cpa16(sbase + STGV  + so, V    + base + (size_t)(lb_ + row) * STRIDE_L + c16 * 4); \
    }                                                                            \
    cpa_commit();                                                                \
} while (0)

#define K5_CVT(CH, B) do {                                                       \
    unsigned bo_ = (unsigned)(B) * 32768u;                                       \
    _Pragma("unroll")                                                            \
    for (int it = 0; it < 4; it++) {                                             \
        int row = rgrp + it * 8;                                                 \
        unsigned so = (unsigned)(row * 512 + c16 * 16);                          \
        float a = ((float*)(smb + ALF))[(CH) * 32 + row];                        \
        float4 pk = *(float4*)(smb + STGPK + so);                                \
        float4 vv = *(float4*)(smb + STGV + so);                                 \
        pk.x *= a; pk.y *= a; pk.z *= a; pk.w *= a;                              \
        ksa[0] += pk.x; ksa[1] += pk.y; ksa[2] += pk.z; ksa[3] += pk.w;          \
        unsigned h01, l01, h23, l23;                                             \
        unsigned off = bo_ + swz256((unsigned)(row * 256 + c16 * 8));            \
        cvt2_hilo(pk.x, pk.y, h01, l01); cvt2_hilo(pk.z, pk.w, h23, l23);        \
        *(uint2*)(smb + off)          = make_uint2(h01, h23);                    \
        *(uint2*)(smb + off + 8192)   = make_uint2(l01, l23);                    \
        cvt2_hilo(vv.x, vv.y, h01, l01); cvt2_hilo(vv.z, vv.w, h23, l23);        \
        *(uint2*)(smb + off + 16384)  = make_uint2(h01, h23);                    \
        *(uint2*)(smb + off + 24576)  = make_uint2(l01, l23);                    \
    }                                                                            \
} while (0)

    K5_CPA(0);
    cpa_wait0();
    K5_CVT(0, 0);
    __syncthreads();

    for (int ch = 0; ch < NCH; ch++) {
        if (ch + 1 < NCH) K5_CPA(ch + 1);
        unsigned bo = (unsigned)(ch & 1) * 32768u;
#pragma unroll
        for (int kk = 0; kk < 2; kk++) {
            unsigned ah[2][4], al[2][4];
#pragma unroll
            for (int mt = 0; mt < 2; mt++) {
                unsigned row = kk * 16 + ((lane >> 4) & 1) * 8 + (lane & 7);
                unsigned col = (warpM + mt * 16) * 2 + ((lane >> 3) & 1) * 16;
                unsigned aoff = bo + swz256(row * 256 + col);
                ldsm4t(ah[mt], sbase + aoff);
                ldsm4t(al[mt], sbase + aoff + 8192);
            }
#pragma unroll
            for (int np = 0; np < 4; np++) {
                unsigned bhr[4], blr[4];
                unsigned brow = kk * 16 + ((lane >> 3) & 1) * 8 + (lane & 7);
                unsigned bcol = (warpN + np * 16) * 2 + ((lane >> 4) & 1) * 16;
                unsigned boff = bo + swz256(brow * 256 + bcol);
                ldsm4t(bhr, sbase + boff + 16384);
                ldsm4t(blr, sbase + boff + 24576);
#pragma unroll
                for (int mt = 0; mt < 2; mt++) {
                    mma16816(acc[mt][np*2],   ah[mt], bhr[0], bhr[1]);
                    mma16816(acc[mt][np*2+1], ah[mt], bhr[2], bhr[3]);
                }
#pragma unroll
                for (int mt = 0; mt < 2; mt++) {
                    mma16816(acc[mt][np*2],   al[mt], bhr[0], bhr[1]);
                    mma16816(acc[mt][np*2+1], al[mt], bhr[2], bhr[3]);
                }
#pragma unroll
                for (int mt = 0; mt < 2; mt++) {
                    mma16816(acc[mt][np*2],   ah[mt], blr[0], blr[1]);
                    mma16816(acc[mt][np*2+1], ah[mt], blr[2], blr[3]);
                }
            }
        }
        if (ch + 1 < NCH) {
            cpa_wait0();
            K5_CVT(ch + 1, (ch + 1) & 1);
        }
        __syncthreads();
    }

    float* dstb = g_kvpart + (size_t)(bh * KSPLITS + split) * DD * DD;
    int g = lane >> 2, qc = (lane & 3) * 2;
#pragma unroll
    for (int mt = 0; mt < 2; mt++)
#pragma unroll
        for (int nt = 0; nt < 8; nt++) {
            int row = warpM + mt * 16 + g;
            int col = warpN + nt * 8 + qc;
            *(float2*)&dstb[(size_t)row * DD + col]       = make_float2(acc[mt][nt][0], acc[mt][nt][1]);
            *(float2*)&dstb[(size_t)(row + 8) * DD + col] = make_float2(acc[mt][nt][2], acc[mt][nt][3]);
        }

    *(float4*)(smb + STGPK + (rgrp * DD + c16 * 4) * 4) = make_float4(ksa[0], ksa[1], ksa[2], ksa[3]);
    __syncthreads();
    if (tid < 32) {
        float4 s = make_float4(0.f, 0.f, 0.f, 0.f);
#pragma unroll
        for (int r = 0; r < 8; r++) {
            float4 v = *(float4*)(smb + STGPK + (r * DD + tid * 4) * 4);
            s.x += v.x; s.y += v.y; s.z += v.z; s.w += v.w;
        }
        *(float4*)(g_ksumpart + (bh * KSPLITS + split) * DD + tid * 4) = s;
    }
}

// ---------------- K6: parallel reduce -> ksum + KVT bf16 hi/lo ----------------
__global__ void __launch_bounds__(256) k6_reduce() {
    __shared__ float accT[32][129];
    __shared__ unsigned oh[32][64];
    __shared__ unsigned ol[32][64];

    int ex = blockIdx.x, bh = blockIdx.y, tid = threadIdx.x;
    int e0 = ex * 32;

    for (int idx = tid; idx < 128 * 32; idx += 256) {
        int d = idx >> 5, el = idx & 31;
        float s = 0.f;
#pragma unroll
        for (int sp = 0; sp < KSPLITS; sp++)
            s += g_kvpart[(size_t)(bh * KSPLITS + sp) * DD * DD + d * DD + e0 + el];
        accT[el][d] = s;
    }
    if (ex == 0 && tid < DD) {
        float s = 0.f;
#pragma unroll
        for (int sp = 0; sp < KSPLITS; sp++) s += g_ksumpart[(bh * KSPLITS + sp) * DD + tid];
        g_ksum[bh * DD + tid] = s;
    }
    __syncthreads();
    for (int idx = tid; idx < 32 * 64; idx += 256) {
        int el = idx >> 6, i = idx & 63;
        unsigned hi, lo;
        cvt2_hilo(accT[el][2 * i], accT[el][2 * i + 1], hi, lo);
        oh[el][i] = hi;
        ol[el][i] = lo;
    }
    __syncthreads();
    for (int idx = tid; idx < 32 * 64; idx += 256) {
        int el = idx >> 6, c = idx & 63;
        size_t di = (size_t)(bh * DD + e0 + el) * (DD/2) + c;
        g_kvT_hi[di] = oh[el][c];
        g_kvT_lo[di] = ol[el][c];
    }
}

// ---------------- K7: resident-B (cp.async), double-buffered-A HMMA GEMM ----------------
// grid (LL/128, BH), block 256, dyn smem 114688
__global__ void __launch_bounds__(256, 2) k7_gemm(const float* __restrict__ phiQ,
                                                  float* __restrict__ out) {
    extern __shared__ __align__(16) unsigned char smb[];
    unsigned sbase = smem_u32(smb);
    __shared__ float sden[DD];
    __shared__ float ksp[DD];
    const unsigned BLOQ = 32768u, AB = 65536u, STGQ = 98304u;

    int chunk = blockIdx.x, bh = blockIdx.y, tid = threadIdx.x;
    int wid = tid >> 5, lane = tid & 31;
    int warpM = (wid >> 1) * 32, warpN = (wid & 1) * 64;
    size_t base = head_base(bh);
    int l0 = chunk * 128;

    if (tid < DD) ksp[tid] = g_ksum[bh * DD + tid];
    // B load via cp.async (folded into chunk-0 commit group)
    for (int idx = tid; idx < 2048; idx += 256) {
        int r = idx >> 4, c16 = idx & 15;
        size_t src = (size_t)(bh * DD + r) * (DD/2) + c16 * 4;
        unsigned off = swz256((unsigned)(r * 256 + c16 * 16));
        cpa16(sbase + off,        g_kvT_hi + src);
        cpa16(sbase + BLOQ + off, g_kvT_lo + src);
    }

    float acc[2][8][4];
#pragma unroll
    for (int mt = 0; mt < 2; mt++)
#pragma unroll
        for (int nt = 0; nt < 8; nt++)
#pragma unroll
            for (int c = 0; c < 4; c++) acc[mt][nt][c] = 0.f;
    float denAcc[4] = {0.f, 0.f, 0.f, 0.f};

#define K7_CPA(CH) do {                                                               \
    _Pragma("unroll")                                                                 \
    for (int it = 0; it < 4; it++) {                                                  \
        int idx = tid + it * 256;                                                     \
        int row = idx >> 3, c4 = idx & 7;                                             \
        cpa16(sbase + STGQ + (unsigned)(row * 128 + c4 * 16),                         \
              phiQ + base + (size_t)(l0 + row) * STRIDE_L + (CH) * 32 + c4 * 4);      \
    }                                                                                 \
    cpa_commit();                                                                     \
} while (0)

#define K7_CVT(CH, B_) do {                                                           \
    unsigned ab_ = AB + (unsigned)(B_) * 16384u;                                      \
    _Pragma("unroll")                                                                 \
    for (int it = 0; it < 4; it++) {                                                  \
        int idx = tid + it * 256;                                                     \
        int row = idx >> 3, c4 = idx & 7;                                             \
        int dg = (CH) * 32 + c4 * 4;                                                  \
        float4 v = *(float4*)(smb + STGQ + (unsigned)(row * 128 + c4 * 16));          \
        float p = v.x * ksp[dg] + v.y * ksp[dg+1] + v.z * ksp[dg+2] + v.w * ksp[dg+3];\
        p += __shfl_xor_sync(0xffffffffu, p, 4);                                      \
        p += __shfl_xor_sync(0xffffffffu, p, 2);                                      \
        p += __shfl_xor_sync(0xffffffffu, p, 1);                                      \
        denAcc[it] += p;                                                              \
        unsigned h01, l01, h23, l23;                                                  \
        cvt2_hilo(v.x, v.y, h01, l01);                                                \
        cvt2_hilo(v.z, v.w, h23, l23);                                                \
        unsigned off = ab_ + sw64b((unsigned)(row * 64 + c4 * 8));                    \
        *(uint2*)(smb + off)        = make_uint2(h01, h23);                           \
        *(uint2*)(smb + off + 8192) = make_uint2(l01, l23);                           \
    }                                                                                 \
} while (0)

    K7_CPA(0);
    __syncthreads();     // order ksp stores before CVT reads (race fix)

    for (int ch = 0; ch < 4; ch++) {
        cpa_wait0();
        K7_CVT(ch, ch & 1);
        __syncthreads();
        if (ch + 1 < 4) K7_CPA(ch + 1);
        unsigned ab = AB + (unsigned)(ch & 1) * 16384u;
#pragma unroll
        for (int kk = 0; kk < 2; kk++) {
            unsigned ah[2][4], al[2][4];
#pragma unroll
            for (int mt = 0; mt < 2; mt++) {
                unsigned aoff = ab + sw64b((warpM + mt * 16 + (lane & 15)) * 64
                                           + kk * 32 + (lane >> 4) * 16);
                ldsm4(ah[mt], sbase + aoff);
                ldsm4(al[mt], sbase + aoff + 8192);
            }
#pragma unroll
            for (int np = 0; np < 4; np++) {
                unsigned bhr[4], blr[4];
                unsigned boff = swz256((warpN + (np * 2 + (lane >> 4)) * 8 + (lane & 7)) * 256
                                       + ch * 64 + kk * 32 + ((lane >> 3) & 1) * 16);
                ldsm4(bhr, sbase + boff);
                ldsm4(blr, sbase + boff + BLOQ);
#pragma unroll
                for (int mt = 0; mt < 2; mt++) {
                    mma16816(acc[mt][np*2],   ah[mt], bhr[0], bhr[1]);
                    mma16816(acc[mt][np*2+1], ah[mt], bhr[2], bhr[3]);
                }
#pragma unroll
                for (int mt = 0; mt < 2; mt++) {
                    mma16816(acc[mt][np*2],   al[mt], bhr[0], bhr[1]);
                    mma16816(acc[mt][np*2+1], al[mt], bhr[2], bhr[3]);
                }
#pragma unroll
                for (int mt = 0; mt < 2; mt++) {
                    mma16816(acc[mt][np*2],   ah[mt], blr[0], blr[1]);
                    mma16816(acc[mt][np*2+1], ah[mt], blr[2], blr[3]);
                }
            }
        }
    }

    __syncthreads();
    if ((tid & 7) == 0) {
#pragma unroll
        for (int it = 0; it < 4; it++) sden[(tid >> 3) + it * 32] = denAcc[it] + EPS;
    }
    __syncthreads();

    int g = lane >> 2, qc = (lane & 3) * 2;
#pragma unroll
    for (int mt = 0; mt < 2; mt++) {
        int row = warpM + mt * 16 + g;
        float d0 = 1.0f / sden[row], d1 = 1.0f / sden[row + 8];
#pragma unroll
        for (int nt = 0; nt < 8; nt++) {
            int col = warpN + nt * 8 + qc;
            float* p0 = out + base + (size_t)(l0 + row) * STRIDE_L + col;
            float* p1 = out + base + (size_t)(l0 + row + 8) * STRIDE_L + col;
            *(float2*)p0 = make_float2(acc[mt][nt][0] * d0, acc[mt][nt][1] * d0);
            *(float2*)p1 = make_float2(acc[mt][nt][2] * d1, acc[mt][nt][3] * d1);
        }
    }
}

// ---------------- launch ----------------
extern "C" void kernel_launch(void* const* d_in, const int* in_sizes, int n_in,
                              void* d_out, int out_size) {
    const float* Q    = (const float*)d_in[0];
    const float* K    = (const float*)d_in[1];
    const float* V    = (const float*)d_in[2];
    const float* phiQ = (const float*)d_in[3];
    const float* phiK = (const float*)d_in[4];
    float* out = (float*)d_out;

    static bool attr_set = false;
    if (!attr_set) {
        cudaFuncSetAttribute(k5_gemm, cudaFuncAttributeMaxDynamicSharedMemorySize, 100352);
        cudaFuncSetAttribute(k7_gemm, cudaFuncAttributeMaxDynamicSharedMemorySize, 114688);
        attr_set = true;
    }

    k_qsum<<<dim3(QSPLITS, BH), 128>>>(Q);
    k_scores<<<dim3(BH, LL / 8), 256>>>(K);
    k5_gemm<<<dim3(KSPLITS, BH), 256, 100352>>>(phiK, V);
    k6_reduce<<<dim3(4, BH), 256>>>();
    k7_gemm<<<dim3(LL/128, BH), 256, 114688>>>(phiQ, out);
}